// round 11
// baseline (speedup 1.0000x reference)
#include <cuda_runtime.h>
#include <math.h>

// Problem constants (fixed shapes from reference: B=4, C=128, H=W=256)
constexpr int BDIM   = 256;
constexpr int NB     = 4096;          // histogram bins per level (static smem budget)
constexpr int HW     = 65536;         // H*W
constexpr unsigned KSEL = 32768;      // k = 0.5*H*W
constexpr int CCH    = 128;
constexpr int BB     = 4;
constexpr int NSLICE = CCH * BB;      // 512 (c,b) slices
constexpr int CPT    = NB / BDIM;     // 16 bins per thread in select scans

// Scratch: entropy values (same layout as hsi), per-slice results.
__device__ float  g_ent[(size_t)NSLICE * HW];   // 134 MB static scratch
__device__ double g_S[NSLICE];                  // total entropy sum per slice
__device__ double g_T[NSLICE];                  // top-k entropy sum per slice

__device__ __forceinline__ unsigned key1_of(float e) {
    unsigned u = __float_as_uint(e);
    if (u & 0x80000000u) u = 0u;                 // negatives / -0.0 -> bin 0
    return min(u >> 18, (unsigned)(NB - 1));
}

__device__ __forceinline__ double blockReduceD(double v, double* dred) {
    int lane = threadIdx.x & 31;
    int wid  = threadIdx.x >> 5;
    #pragma unroll
    for (int o = 16; o > 0; o >>= 1) v += __shfl_down_sync(0xffffffffu, v, o);
    if (lane == 0) dred[wid] = v;
    __syncthreads();
    double r;
    if (wid == 0) {
        r = (lane < BDIM / 32) ? dred[lane] : 0.0;
        #pragma unroll
        for (int o = 16; o > 0; o >>= 1) r += __shfl_down_sync(0xffffffffu, r, o);
        if (lane == 0) dred[0] = r;
    }
    __syncthreads();
    r = dred[0];
    __syncthreads();   // protect dred for reuse
    return r;
}

// Find bin b and cnt_gt = count(elements in bins > b) such that
// cnt_gt < k <= cnt_gt + hist[b].  Results broadcast via bcast[0]=b, bcast[1]=cnt_gt.
__device__ __forceinline__ void selectBin(const unsigned int* hist, unsigned int* chunk,
                                          unsigned int k, unsigned int* bcast) {
    const int t = threadIdx.x;
    const unsigned base = (unsigned)t * CPT;
    unsigned int ct = 0;
    #pragma unroll
    for (int i = 0; i < CPT; i++) ct += hist[base + i];
    chunk[t] = ct;
    // inclusive suffix sum over chunks (Kogge-Stone)
    for (int off = 1; off < BDIM; off <<= 1) {
        __syncthreads();
        unsigned int add = (t + off < BDIM) ? chunk[t + off] : 0u;
        __syncthreads();
        chunk[t] += add;
    }
    __syncthreads();
    unsigned int incl = chunk[t];
    unsigned int suf  = incl - ct;   // count strictly above this chunk
    if (suf < k && k <= incl) {      // exactly one thread matches
        unsigned int running = suf;
        #pragma unroll
        for (int i = CPT - 1; i >= 0; i--) {
            unsigned int c = hist[base + i];
            if (running < k && k <= running + c) {
                bcast[0] = base + (unsigned)i;
                bcast[1] = running;
                break;
            }
            running += c;
        }
    }
    __syncthreads();
}

__global__ void __launch_bounds__(BDIM)
k_main(const float* __restrict__ hsi, const float* __restrict__ wp) {
    __shared__ unsigned int s_hist[NB];     // 16 KB
    __shared__ float        s_hsum[NB];     // 16 KB
    __shared__ unsigned int s_chunk[BDIM];  // 1 KB
    __shared__ double       s_dred[32];
    __shared__ unsigned int s_bcast[2];

    const int t = threadIdx.x;
    const int s = blockIdx.x;                 // slice id (memory-linear: b = s/CCH, c = s%CCH)
    const float wv = wp[0];

    const float4* __restrict__ in = reinterpret_cast<const float4*>(hsi + (size_t)s * HW);
    float4* __restrict__ sc = reinterpret_cast<float4*>(g_ent + (size_t)s * HW);

    if (t < 2) s_bcast[t] = 0u;               // deterministic even if select were to miss
    for (int i = t; i < NB; i += BDIM) s_hist[i] = 0u;
    __syncthreads();

    // ---- Pass A: entropy compute + scratch write + total sum + level-1 count hist ----
    double lsum = 0.0;
    #pragma unroll 4
    for (int i = t; i < HW / 4; i += BDIM) {
        float4 v = in[i];
        float x0 = v.x * wv, x1 = v.y * wv, x2 = v.z * wv, x3 = v.w * wv;
        float e0 = fmaxf(-x0 * logf(x0), 0.0f);   // fmaxf kills NaN and -0.0
        float e1 = fmaxf(-x1 * logf(x1), 0.0f);
        float e2 = fmaxf(-x2 * logf(x2), 0.0f);
        float e3 = fmaxf(-x3 * logf(x3), 0.0f);
        sc[i] = make_float4(e0, e1, e2, e3);
        lsum += (double)e0 + (double)e1 + (double)e2 + (double)e3;
        atomicAdd(&s_hist[key1_of(e0)], 1u);
        atomicAdd(&s_hist[key1_of(e1)], 1u);
        atomicAdd(&s_hist[key1_of(e2)], 1u);
        atomicAdd(&s_hist[key1_of(e3)], 1u);
    }
    __syncthreads();

    double Ssum = blockReduceD(lsum, s_dred);

    // ---- Level-1 select ----
    selectBin(s_hist, s_chunk, KSEL, s_bcast);
    const unsigned b1      = s_bcast[0];
    const unsigned cnt_gt1 = s_bcast[1];
    __syncthreads();

    // clear for level-2
    for (int i = t; i < NB; i += BDIM) { s_hist[i] = 0u; s_hsum[i] = 0.0f; }
    __syncthreads();

    // ---- Pass B: sum above level-1 bin; level-2 count+sum hist for boundary bin ----
    double sgt = 0.0;
    #pragma unroll 4
    for (int i = t; i < HW / 4; i += BDIM) {
        float4 e4 = sc[i];
        #pragma unroll
        for (int j = 0; j < 4; j++) {
            float e = (j == 0) ? e4.x : (j == 1) ? e4.y : (j == 2) ? e4.z : e4.w;
            unsigned k1 = key1_of(e);
            if (k1 > b1) {
                sgt += (double)e;
            } else if (k1 == b1) {
                unsigned k2 = (__float_as_uint(e) >> 6) & (unsigned)(NB - 1);
                atomicAdd(&s_hist[k2], 1u);
                atomicAdd(&s_hsum[k2], e);
            }
        }
    }
    __syncthreads();

    double SGT = blockReduceD(sgt, s_dred);

    // ---- Level-2 select ----
    const unsigned kp = KSEL - cnt_gt1;           // in [1, hist1[b1]]
    selectBin(s_hist, s_chunk, kp, s_bcast);
    const unsigned b2      = s_bcast[0];
    const unsigned cnt_gt2 = s_bcast[1];
    __syncthreads();

    // sum of level-2 bins strictly above b2
    double l2 = 0.0;
    for (int i = t; i < NB; i += BDIM)
        if ((unsigned)i > b2) l2 += (double)s_hsum[i];
    double SGT2 = blockReduceD(l2, s_dred);

    if (t == 0) {
        unsigned r2  = kp - cnt_gt2;              // in [1, hist2[b2]]
        unsigned cb2 = s_hist[b2];
        double avg = (cb2 > 0) ? (double)s_hsum[b2] / (double)cb2 : 0.0;
        g_S[s] = Ssum;
        g_T[s] = SGT + SGT2 + (double)r2 * avg;
    }
}

__global__ void k_final(float* __restrict__ out) {
    __shared__ double d[CCH];
    const int c = threadIdx.x;
    if (c < CCH) {
        double S = 0.0, T = 0.0;
        #pragma unroll
        for (int b = 0; b < BB; b++) {
            S += g_S[b * CCH + c];
            T += g_T[b * CCH + c];
        }
        double mean      = S / ((double)BB * (double)HW);
        double mean_high = T / ((double)BB * (double)KSEL);
        d[c] = 2.0 * (mean_high - mean);
    }
    __syncthreads();
    if (c == 0) {
        #pragma unroll
        for (int j = 0; j < 3; j++) {
            int bi = -1; double bv = 0.0;
            for (int i = 0; i < CCH; i++) {
                // first valid (non-NaN) entry seeds; strict > keeps lowest idx on ties
                if (bi < 0 ? (d[i] == d[i]) : (d[i] > bv)) { bv = d[i]; bi = i; }
            }
            if (bi < 0) bi = j;                    // fully-NaN fallback: deterministic
            out[j] = (float)bi;                    // FLOAT32 output: indices as f32 values
            d[bi] = -1e300;
        }
    }
}

extern "C" void kernel_launch(void* const* d_in, const int* in_sizes, int n_in,
                              void* d_out, int out_size) {
    // Robust input selection: hsi is the big tensor (16,777,216 elems), w is scalar.
    const float* hsi = (const float*)d_in[0];
    const float* w   = (n_in > 1) ? (const float*)d_in[1] : (const float*)d_in[0];
    if (n_in > 1 && in_sizes[0] < in_sizes[1]) {
        hsi = (const float*)d_in[1];
        w   = (const float*)d_in[0];
    }
    float* out = (float*)d_out;

    k_main<<<NSLICE, BDIM>>>(hsi, w);
    k_final<<<1, 128>>>(out);
}

// round 12
// speedup vs baseline: 4.1849x; 4.1849x over previous
#include <cuda_runtime.h>
#include <math.h>

// Problem constants (fixed shapes from reference: B=4, C=128, H=W=256)
constexpr int BDIM   = 256;
constexpr int NB     = 4096;          // histogram bins per level (static smem budget)
constexpr int HW     = 65536;         // H*W
constexpr unsigned KSEL = 32768;      // k = 0.5*H*W
constexpr int CCH    = 128;
constexpr int BB     = 4;
constexpr int NSLICE = CCH * BB;      // 512 (c,b) slices
constexpr int CPT    = NB / BDIM;     // 16 bins per thread in select scans

// Scratch: entropy values (same layout as hsi), per-slice results.
__device__ float  g_ent[(size_t)NSLICE * HW];   // 134 MB static scratch
__device__ double g_S[NSLICE];                  // total entropy sum per slice
__device__ double g_T[NSLICE];                  // top-k entropy sum per slice

__device__ __forceinline__ unsigned key1_of(float e) {
    unsigned u = __float_as_uint(e);
    if (u & 0x80000000u) u = 0u;                 // negatives / -0.0 -> bin 0
    return min(u >> 18, (unsigned)(NB - 1));
}

__device__ __forceinline__ double blockReduceD(double v, double* dred) {
    int lane = threadIdx.x & 31;
    int wid  = threadIdx.x >> 5;
    #pragma unroll
    for (int o = 16; o > 0; o >>= 1) v += __shfl_down_sync(0xffffffffu, v, o);
    if (lane == 0) dred[wid] = v;
    __syncthreads();
    double r;
    if (wid == 0) {
        r = (lane < BDIM / 32) ? dred[lane] : 0.0;
        #pragma unroll
        for (int o = 16; o > 0; o >>= 1) r += __shfl_down_sync(0xffffffffu, r, o);
        if (lane == 0) dred[0] = r;
    }
    __syncthreads();
    r = dred[0];
    __syncthreads();   // protect dred for reuse
    return r;
}

// Find bin b and cnt_gt = count(elements in bins > b) such that
// cnt_gt < k <= cnt_gt + hist[b].  Results broadcast via bcast[0]=b, bcast[1]=cnt_gt.
__device__ __forceinline__ void selectBin(const unsigned int* hist, unsigned int* chunk,
                                          unsigned int k, unsigned int* bcast) {
    const int t = threadIdx.x;
    const unsigned base = (unsigned)t * CPT;
    unsigned int ct = 0;
    #pragma unroll
    for (int i = 0; i < CPT; i++) ct += hist[base + i];
    chunk[t] = ct;
    // inclusive suffix sum over chunks (Kogge-Stone)
    for (int off = 1; off < BDIM; off <<= 1) {
        __syncthreads();
        unsigned int add = (t + off < BDIM) ? chunk[t + off] : 0u;
        __syncthreads();
        chunk[t] += add;
    }
    __syncthreads();
    unsigned int incl = chunk[t];
    unsigned int suf  = incl - ct;   // count strictly above this chunk
    if (suf < k && k <= incl) {      // exactly one thread matches
        unsigned int running = suf;
        #pragma unroll
        for (int i = CPT - 1; i >= 0; i--) {
            unsigned int c = hist[base + i];
            if (running < k && k <= running + c) {
                bcast[0] = base + (unsigned)i;
                bcast[1] = running;
                break;
            }
            running += c;
        }
    }
    __syncthreads();
}

__global__ void __launch_bounds__(BDIM)
k_main(const float* __restrict__ hsi, const float* __restrict__ wp) {
    __shared__ unsigned int s_hist[NB];     // 16 KB
    __shared__ float        s_hsum[NB];     // 16 KB
    __shared__ unsigned int s_chunk[BDIM];  // 1 KB
    __shared__ double       s_dred[32];
    __shared__ unsigned int s_bcast[2];

    const int t = threadIdx.x;
    const int s = blockIdx.x;                 // slice id (memory-linear: b = s/CCH, c = s%CCH)
    const float wv = wp[0];

    const float4* __restrict__ in = reinterpret_cast<const float4*>(hsi + (size_t)s * HW);
    float4* __restrict__ sc = reinterpret_cast<float4*>(g_ent + (size_t)s * HW);

    if (t < 2) s_bcast[t] = 0u;
    for (int i = t; i < NB; i += BDIM) s_hist[i] = 0u;
    __syncthreads();

    // ---- Pass A: entropy (fast log) + scratch write + float lane-sums + level-1 hist ----
    float a0 = 0.f, a1 = 0.f, a2 = 0.f, a3 = 0.f;   // per-lane float accumulators (64 adds each)
    #pragma unroll 4
    for (int i = t; i < HW / 4; i += BDIM) {
        float4 v = in[i];
        float x0 = v.x * wv, x1 = v.y * wv, x2 = v.z * wv, x3 = v.w * wv;
        float e0 = fmaxf(-x0 * __logf(x0), 0.0f);   // fmaxf kills NaN and -0.0
        float e1 = fmaxf(-x1 * __logf(x1), 0.0f);
        float e2 = fmaxf(-x2 * __logf(x2), 0.0f);
        float e3 = fmaxf(-x3 * __logf(x3), 0.0f);
        sc[i] = make_float4(e0, e1, e2, e3);
        a0 += e0; a1 += e1; a2 += e2; a3 += e3;
        atomicAdd(&s_hist[key1_of(e0)], 1u);
        atomicAdd(&s_hist[key1_of(e1)], 1u);
        atomicAdd(&s_hist[key1_of(e2)], 1u);
        atomicAdd(&s_hist[key1_of(e3)], 1u);
    }
    __syncthreads();

    double lsum = ((double)a0 + (double)a1) + ((double)a2 + (double)a3);
    double Ssum = blockReduceD(lsum, s_dred);

    // ---- Level-1 select ----
    selectBin(s_hist, s_chunk, KSEL, s_bcast);
    const unsigned b1      = s_bcast[0];
    const unsigned cnt_gt1 = s_bcast[1];
    __syncthreads();

    // clear for level-2
    for (int i = t; i < NB; i += BDIM) { s_hist[i] = 0u; s_hsum[i] = 0.0f; }
    __syncthreads();

    // ---- Pass B: sum above level-1 bin (float accum); level-2 hist for boundary bin ----
    float g0 = 0.f, g1 = 0.f, g2 = 0.f, g3 = 0.f;
    #pragma unroll 4
    for (int i = t; i < HW / 4; i += BDIM) {
        float4 e4 = sc[i];
        unsigned ka = key1_of(e4.x), kb = key1_of(e4.y);
        unsigned kc = key1_of(e4.z), kd = key1_of(e4.w);
        if (ka > b1) g0 += e4.x;
        else if (ka == b1) {
            unsigned k2 = (__float_as_uint(e4.x) >> 6) & (unsigned)(NB - 1);
            atomicAdd(&s_hist[k2], 1u); atomicAdd(&s_hsum[k2], e4.x);
        }
        if (kb > b1) g1 += e4.y;
        else if (kb == b1) {
            unsigned k2 = (__float_as_uint(e4.y) >> 6) & (unsigned)(NB - 1);
            atomicAdd(&s_hist[k2], 1u); atomicAdd(&s_hsum[k2], e4.y);
        }
        if (kc > b1) g2 += e4.z;
        else if (kc == b1) {
            unsigned k2 = (__float_as_uint(e4.z) >> 6) & (unsigned)(NB - 1);
            atomicAdd(&s_hist[k2], 1u); atomicAdd(&s_hsum[k2], e4.z);
        }
        if (kd > b1) g3 += e4.w;
        else if (kd == b1) {
            unsigned k2 = (__float_as_uint(e4.w) >> 6) & (unsigned)(NB - 1);
            atomicAdd(&s_hist[k2], 1u); atomicAdd(&s_hsum[k2], e4.w);
        }
    }
    __syncthreads();

    double sgt = ((double)g0 + (double)g1) + ((double)g2 + (double)g3);
    double SGT = blockReduceD(sgt, s_dred);

    // ---- Level-2 select ----
    const unsigned kp = KSEL - cnt_gt1;           // in [1, hist1[b1]]
    selectBin(s_hist, s_chunk, kp, s_bcast);
    const unsigned b2      = s_bcast[0];
    const unsigned cnt_gt2 = s_bcast[1];
    __syncthreads();

    // sum of level-2 bins strictly above b2
    double l2 = 0.0;
    for (int i = t; i < NB; i += BDIM)
        if ((unsigned)i > b2) l2 += (double)s_hsum[i];
    double SGT2 = blockReduceD(l2, s_dred);

    if (t == 0) {
        unsigned r2  = kp - cnt_gt2;              // in [1, hist2[b2]]
        unsigned cb2 = s_hist[b2];
        double avg = (cb2 > 0) ? (double)s_hsum[b2] / (double)cb2 : 0.0;
        g_S[s] = Ssum;
        g_T[s] = SGT + SGT2 + (double)r2 * avg;
    }
}

__global__ void k_final(float* __restrict__ out) {
    __shared__ double d[CCH];
    __shared__ double sv[CCH];
    __shared__ int    si[CCH];
    const int c = threadIdx.x;
    if (c < CCH) {
        double S = 0.0, T = 0.0;
        #pragma unroll
        for (int b = 0; b < BB; b++) {
            S += g_S[b * CCH + c];
            T += g_T[b * CCH + c];
        }
        double mean      = S / ((double)BB * (double)HW);
        double mean_high = T / ((double)BB * (double)KSEL);
        d[c] = 2.0 * (mean_high - mean);
    }
    __syncthreads();
    #pragma unroll
    for (int j = 0; j < 3; j++) {
        if (c < CCH) { sv[c] = d[c]; si[c] = c; }
        __syncthreads();
        #pragma unroll
        for (int off = CCH / 2; off > 0; off >>= 1) {
            if (c < off) {
                double ov = sv[c + off]; int oi = si[c + off];
                // argsort(-delta) stable: larger value wins; on tie, lower index wins
                if (ov > sv[c] || (ov == sv[c] && oi < si[c])) { sv[c] = ov; si[c] = oi; }
            }
            __syncthreads();
        }
        if (c == 0) {
            out[j] = (float)si[0];                 // FLOAT32 output: indices as f32 values
            d[si[0]] = -1e300;                     // remove winner for next round
        }
        __syncthreads();
    }
}

extern "C" void kernel_launch(void* const* d_in, const int* in_sizes, int n_in,
                              void* d_out, int out_size) {
    // Robust input selection: hsi is the big tensor (16,777,216 elems), w is scalar.
    const float* hsi = (const float*)d_in[0];
    const float* w   = (n_in > 1) ? (const float*)d_in[1] : (const float*)d_in[0];
    if (n_in > 1 && in_sizes[0] < in_sizes[1]) {
        hsi = (const float*)d_in[1];
        w   = (const float*)d_in[0];
    }
    float* out = (float*)d_out;

    k_main<<<NSLICE, BDIM>>>(hsi, w);
    k_final<<<1, 128>>>(out);
}

// round 13
// speedup vs baseline: 5.0474x; 1.2061x over previous
#include <cuda_runtime.h>
#include <math.h>

// Problem constants (fixed shapes from reference: B=4, C=128, H=W=256)
constexpr int BDIM   = 256;
constexpr int NB     = 4096;          // histogram bins per level (static smem budget)
constexpr int HW     = 65536;         // H*W
constexpr unsigned KSEL = 32768;      // k = 0.5*H*W
constexpr int CCH    = 128;
constexpr int BB     = 4;
constexpr int NSLICE = CCH * BB;      // 512 (c,b) slices
constexpr int CPT    = NB / BDIM;     // 16 bins per thread in select scans

__device__ double g_S[NSLICE];                  // total entropy sum per slice
__device__ double g_T[NSLICE];                  // top-k entropy sum per slice
__device__ unsigned int g_done = 0;             // CTA completion counter (reset each launch)

__device__ __forceinline__ unsigned key1_of(float e) {
    unsigned u = __float_as_uint(e);
    if (u & 0x80000000u) u = 0u;                 // negatives / -0.0 -> bin 0
    return min(u >> 18, (unsigned)(NB - 1));
}

__device__ __forceinline__ float ent_of(float x) {
    return fmaxf(-x * __logf(x), 0.0f);          // fmaxf kills NaN and -0.0
}

__device__ __forceinline__ double blockReduceD(double v, double* dred) {
    int lane = threadIdx.x & 31;
    int wid  = threadIdx.x >> 5;
    #pragma unroll
    for (int o = 16; o > 0; o >>= 1) v += __shfl_down_sync(0xffffffffu, v, o);
    if (lane == 0) dred[wid] = v;
    __syncthreads();
    double r;
    if (wid == 0) {
        r = (lane < BDIM / 32) ? dred[lane] : 0.0;
        #pragma unroll
        for (int o = 16; o > 0; o >>= 1) r += __shfl_down_sync(0xffffffffu, r, o);
        if (lane == 0) dred[0] = r;
    }
    __syncthreads();
    r = dred[0];
    __syncthreads();   // protect dred for reuse
    return r;
}

// Find bin b and cnt_gt = count(elements in bins > b) such that
// cnt_gt < k <= cnt_gt + hist[b].  Results broadcast via bcast[0]=b, bcast[1]=cnt_gt.
__device__ __forceinline__ void selectBin(const unsigned int* hist, unsigned int* chunk,
                                          unsigned int k, unsigned int* bcast) {
    const int t = threadIdx.x;
    const unsigned base = (unsigned)t * CPT;
    unsigned int ct = 0;
    #pragma unroll
    for (int i = 0; i < CPT; i++) ct += hist[base + i];
    chunk[t] = ct;
    // inclusive suffix sum over chunks (Kogge-Stone)
    for (int off = 1; off < BDIM; off <<= 1) {
        __syncthreads();
        unsigned int add = (t + off < BDIM) ? chunk[t + off] : 0u;
        __syncthreads();
        chunk[t] += add;
    }
    __syncthreads();
    unsigned int incl = chunk[t];
    unsigned int suf  = incl - ct;   // count strictly above this chunk
    if (suf < k && k <= incl) {      // exactly one thread matches
        unsigned int running = suf;
        #pragma unroll
        for (int i = CPT - 1; i >= 0; i--) {
            unsigned int c = hist[base + i];
            if (running < k && k <= running + c) {
                bcast[0] = base + (unsigned)i;
                bcast[1] = running;
                break;
            }
            running += c;
        }
    }
    __syncthreads();
}

__global__ void __launch_bounds__(BDIM)
k_main(const float* __restrict__ hsi, const float* __restrict__ wp,
       float* __restrict__ out) {
    __shared__ unsigned int s_hist[NB];     // 16 KB
    __shared__ float        s_hsum[NB];     // 16 KB
    __shared__ unsigned int s_chunk[BDIM];  // 1 KB
    __shared__ double       s_dred[32];
    __shared__ unsigned int s_bcast[2];
    __shared__ int          s_last;

    const int t = threadIdx.x;
    const int s = blockIdx.x;                 // slice id (memory-linear: b = s/CCH, c = s%CCH)
    const float wv = wp[0];

    const float4* __restrict__ in = reinterpret_cast<const float4*>(hsi + (size_t)s * HW);

    if (t < 2) s_bcast[t] = 0u;
    for (int i = t; i < NB; i += BDIM) s_hist[i] = 0u;
    __syncthreads();

    // ---- Pass A: entropy (fast log) + float lane-sums + level-1 count hist ----
    float a0 = 0.f, a1 = 0.f, a2 = 0.f, a3 = 0.f;   // per-lane float accumulators (64 adds each)
    #pragma unroll 4
    for (int i = t; i < HW / 4; i += BDIM) {
        float4 v = in[i];
        float e0 = ent_of(v.x * wv);
        float e1 = ent_of(v.y * wv);
        float e2 = ent_of(v.z * wv);
        float e3 = ent_of(v.w * wv);
        a0 += e0; a1 += e1; a2 += e2; a3 += e3;
        atomicAdd(&s_hist[key1_of(e0)], 1u);
        atomicAdd(&s_hist[key1_of(e1)], 1u);
        atomicAdd(&s_hist[key1_of(e2)], 1u);
        atomicAdd(&s_hist[key1_of(e3)], 1u);
    }
    __syncthreads();

    double lsum = ((double)a0 + (double)a1) + ((double)a2 + (double)a3);
    double Ssum = blockReduceD(lsum, s_dred);

    // ---- Level-1 select ----
    selectBin(s_hist, s_chunk, KSEL, s_bcast);
    const unsigned b1      = s_bcast[0];
    const unsigned cnt_gt1 = s_bcast[1];
    __syncthreads();

    // clear for level-2
    for (int i = t; i < NB; i += BDIM) { s_hist[i] = 0u; s_hsum[i] = 0.0f; }
    __syncthreads();

    // ---- Pass B: re-read input, recompute entropy (bit-identical), sum above b1;
    //      level-2 count+sum hist for boundary bin ----
    float g0 = 0.f, g1 = 0.f, g2 = 0.f, g3 = 0.f;
    #pragma unroll 4
    for (int i = t; i < HW / 4; i += BDIM) {
        float4 v = in[i];
        float e0 = ent_of(v.x * wv);
        float e1 = ent_of(v.y * wv);
        float e2 = ent_of(v.z * wv);
        float e3 = ent_of(v.w * wv);
        unsigned ka = key1_of(e0), kb = key1_of(e1);
        unsigned kc = key1_of(e2), kd = key1_of(e3);
        if (ka > b1) g0 += e0;
        else if (ka == b1) {
            unsigned k2 = (__float_as_uint(e0) >> 6) & (unsigned)(NB - 1);
            atomicAdd(&s_hist[k2], 1u); atomicAdd(&s_hsum[k2], e0);
        }
        if (kb > b1) g1 += e1;
        else if (kb == b1) {
            unsigned k2 = (__float_as_uint(e1) >> 6) & (unsigned)(NB - 1);
            atomicAdd(&s_hist[k2], 1u); atomicAdd(&s_hsum[k2], e1);
        }
        if (kc > b1) g2 += e2;
        else if (kc == b1) {
            unsigned k2 = (__float_as_uint(e2) >> 6) & (unsigned)(NB - 1);
            atomicAdd(&s_hist[k2], 1u); atomicAdd(&s_hsum[k2], e2);
        }
        if (kd > b1) g3 += e3;
        else if (kd == b1) {
            unsigned k2 = (__float_as_uint(e3) >> 6) & (unsigned)(NB - 1);
            atomicAdd(&s_hist[k2], 1u); atomicAdd(&s_hsum[k2], e3);
        }
    }
    __syncthreads();

    double sgt = ((double)g0 + (double)g1) + ((double)g2 + (double)g3);
    double SGT = blockReduceD(sgt, s_dred);

    // ---- Level-2 select ----
    const unsigned kp = KSEL - cnt_gt1;           // in [1, hist1[b1]]
    selectBin(s_hist, s_chunk, kp, s_bcast);
    const unsigned b2      = s_bcast[0];
    const unsigned cnt_gt2 = s_bcast[1];
    __syncthreads();

    // sum of level-2 bins strictly above b2
    double l2 = 0.0;
    for (int i = t; i < NB; i += BDIM)
        if ((unsigned)i > b2) l2 += (double)s_hsum[i];
    double SGT2 = blockReduceD(l2, s_dred);

    if (t == 0) {
        unsigned r2  = kp - cnt_gt2;              // in [1, hist2[b2]]
        unsigned cb2 = s_hist[b2];
        double avg = (cb2 > 0) ? (double)s_hsum[b2] / (double)cb2 : 0.0;
        g_S[s] = Ssum;
        g_T[s] = SGT + SGT2 + (double)r2 * avg;
    }

    // ---- Fused finalization: last CTA to finish reduces 128 channels ----
    __threadfence();
    if (t == 0) {
        unsigned old = atomicAdd(&g_done, 1u);
        s_last = (old == (unsigned)(NSLICE - 1)) ? 1 : 0;
    }
    __syncthreads();
    if (s_last) {
        __shared__ double d[CCH];
        __shared__ double sv[CCH];
        __shared__ int    si[CCH];
        if (t < CCH) {
            double S = 0.0, T = 0.0;
            #pragma unroll
            for (int b = 0; b < BB; b++) {
                S += g_S[b * CCH + t];
                T += g_T[b * CCH + t];
            }
            double mean      = S / ((double)BB * (double)HW);
            double mean_high = T / ((double)BB * (double)KSEL);
            d[t] = 2.0 * (mean_high - mean);
        }
        __syncthreads();
        #pragma unroll
        for (int j = 0; j < 3; j++) {
            if (t < CCH) { sv[t] = d[t]; si[t] = t; }
            __syncthreads();
            #pragma unroll
            for (int off = CCH / 2; off > 0; off >>= 1) {
                if (t < off) {
                    double ov = sv[t + off]; int oi = si[t + off];
                    // argsort(-delta) stable: larger value wins; on tie, lower index wins
                    if (ov > sv[t] || (ov == sv[t] && oi < si[t])) { sv[t] = ov; si[t] = oi; }
                }
                __syncthreads();
            }
            if (t == 0) {
                out[j] = (float)si[0];             // FLOAT32 output: indices as f32 values
                d[si[0]] = -1e300;
            }
            __syncthreads();
        }
        if (t == 0) g_done = 0;                    // reset for next graph replay
    }
}

extern "C" void kernel_launch(void* const* d_in, const int* in_sizes, int n_in,
                              void* d_out, int out_size) {
    // Robust input selection: hsi is the big tensor (16,777,216 elems), w is scalar.
    const float* hsi = (const float*)d_in[0];
    const float* w   = (n_in > 1) ? (const float*)d_in[1] : (const float*)d_in[0];
    if (n_in > 1 && in_sizes[0] < in_sizes[1]) {
        hsi = (const float*)d_in[1];
        w   = (const float*)d_in[0];
    }
    float* out = (float*)d_out;

    k_main<<<NSLICE, BDIM>>>(hsi, w, out);
}